// round 11
// baseline (speedup 1.0000x reference)
#include <cuda_runtime.h>
#include <math.h>

#define N_NODES 100000
#define N_GRAPHS 1000
#define D 64
#define H 128
#define CAP 64            // max in-degree capacity (actual max ~32 for Poisson(10)+ring)
#define ZROW N_NODES      // zero-row index (stays zero: statics zero-init, never written)

// Packed f32x2 add: one instruction = two float adds (register pair operands).
#define ADD_F32X2(out, a, b) \
    asm("add.rn.f32x2 %0, %1, %2;" : "=l"(out) : "l"(a), "l"(b))

// Scratch (alloc-free rule: __device__ globals). cursor/pool/cnt share one
// struct so a single memset clears all per-run state.
struct ZeroRegion {
    int   cursor[N_NODES];      // becomes in-degree after fill
    float pool[N_GRAPHS * D];
    float cnt[N_GRAPHS];
};
__device__ ZeroRegion g_z;
__device__ int   g_esrc[N_NODES * CAP];        // bucketed edge lists (25.6 MB)
__device__ float g_x[(N_NODES + 1) * D];       // +1 zero row for pad loads
__device__ float g_h[(N_NODES + 1) * D];       // +1 zero row for pad loads

// ---------------------------------------------------------------------------
// Bucketed CSR fill: cursor counts in-degree, esrc[d*CAP + pos] = s.
__global__ void fill_kernel(const int* __restrict__ src,
                            const int* __restrict__ dst, int E) {
    int i = blockIdx.x * blockDim.x + threadIdx.x;
    if (i >= E) return;
    int d = dst[i];
    int pos = atomicAdd(&g_z.cursor[d], 1);
    if (pos < CAP) g_esrc[(size_t)d * CAP + pos] = src[i];
}

// ---------------------------------------------------------------------------
// Y[N,64] = (X[N,64] @ W[64,64]) * rsqrt(deg[row]+1)
__global__ void gemm64_kernel(const float* __restrict__ X,
                              const float* __restrict__ W,
                              float* __restrict__ Y) {
    __shared__ float sW[D * D];
    __shared__ float sx[32 * D];
    int t = threadIdx.x;
    int row0 = blockIdx.x * 32;
    for (int i = t; i < D * D; i += 256) sW[i] = W[i];
    for (int i = t; i < 32 * D; i += 256) sx[i] = X[row0 * D + i];
    __syncthreads();
    int j = t & 63;
    int rg = t >> 6;
    float acc[8];
#pragma unroll
    for (int i = 0; i < 8; i++) acc[i] = 0.f;
#pragma unroll
    for (int k = 0; k < D; k++) {
        float w = sW[k * D + j];
#pragma unroll
        for (int i = 0; i < 8; i++)
            acc[i] += sx[(rg * 8 + i) * D + k] * w;
    }
#pragma unroll
    for (int i = 0; i < 8; i++) {
        int row = row0 + rg * 8 + i;
        float di = rsqrtf((float)(min(g_z.cursor[row], CAP) + 1));
        Y[row * D + j] = acc[i] * di;
    }
}

// ---------------------------------------------------------------------------
// Gather, half-warp (16 lanes x 16B) per node. Input pre-scaled by dinv[src].
// Inner loop: fixed-trip 16, fully unrolled, f32x2 packed accumulation:
// per edge per lane = SHFL + LDG.128 + 2x ADD.f32x2.
//   t[n] = dinv[n] * (sum_{s in N(n)} x'[s] + x'[n])
//   MODE 1 (layer 1): out[n] = relu(t[n] + b) * dinv[n]        -> write g_h
//   MODE 0 (layer 2): red.v4  g_z.pool[batch[n]] += t[n]; cnt  -> no z buffer
template <int MODE>
__global__ void gather_kernel(const ulonglong2* __restrict__ Xu,
                              float4* __restrict__ out,
                              const float4* __restrict__ b4,
                              const int* __restrict__ batch) {
    int node = (blockIdx.x * blockDim.x + threadIdx.x) >> 4;
    int lane = threadIdx.x & 31;
    int hl = lane & 15;
    int deg = min(g_z.cursor[node], CAP);
    int maxdeg = max(deg, __shfl_xor_sync(0xffffffffu, deg, 16));
    const int* rowp = g_esrc + (size_t)node * CAP;
    unsigned long long a0 = 0, a1 = 0;   // f32x2 accumulators {0.f,0.f}
    for (int j = 0; j < maxdeg; j += 16) {
        int s = ((j + hl) < deg) ? rowp[j + hl] : ZROW;
#pragma unroll
        for (int i = 0; i < 16; i++) {
            int si = __shfl_sync(0xffffffffu, s, (lane & 16) + i);
            ulonglong2 v = Xu[(size_t)si * 16 + hl];
            ADD_F32X2(a0, a0, v.x);
            ADD_F32X2(a1, a1, v.y);
        }
    }
    // self term
    {
        ulonglong2 v = Xu[(size_t)node * 16 + hl];
        ADD_F32X2(a0, a0, v.x);
        ADD_F32X2(a1, a1, v.y);
    }
    float di = rsqrtf((float)(deg + 1));
    float4 o;
    asm("mov.b64 {%0, %1}, %2;" : "=f"(o.x), "=f"(o.y) : "l"(a0));
    asm("mov.b64 {%0, %1}, %2;" : "=f"(o.z), "=f"(o.w) : "l"(a1));
    o.x *= di; o.y *= di; o.z *= di; o.w *= di;
    if (MODE == 1) {
        float4 bb = b4[hl];
        o.x = fmaxf(o.x + bb.x, 0.f) * di;
        o.y = fmaxf(o.y + bb.y, 0.f) * di;
        o.z = fmaxf(o.z + bb.z, 0.f) * di;
        o.w = fmaxf(o.w + bb.w, 0.f) * di;
        out[(size_t)node * 16 + hl] = o;
    } else {
        int g = __ldg(batch + node);
        float* p = g_z.pool + g * D + hl * 4;
        asm volatile("red.global.add.v4.f32 [%0], {%1, %2, %3, %4};"
                     :: "l"(p), "f"(o.x), "f"(o.y), "f"(o.z), "f"(o.w)
                     : "memory");
        if (hl == 0) atomicAdd(&g_z.cnt[g], 1.f);
    }
}

// ---------------------------------------------------------------------------
// Head: q = mean(z) @ W2 + b2 ; out = sigmoid(relu(q @ mW1 + mb1) @ mW2 + mb2)
__global__ void mlp_kernel(const float* __restrict__ W2,
                           const float* __restrict__ b2,
                           const float* __restrict__ mW1,
                           const float* __restrict__ mb1,
                           const float* __restrict__ mW2,
                           const float* __restrict__ mb2,
                           float* __restrict__ out) {
    __shared__ float p[D];
    __shared__ float q[D];
    __shared__ float red[H];
    int g = blockIdx.x, t = threadIdx.x;
    if (t < D) {
        float c = fmaxf(g_z.cnt[g], 1.f);
        p[t] = g_z.pool[g * D + t] / c;
    }
    __syncthreads();
    if (t < D) {
        float a = b2[t];
#pragma unroll
        for (int k = 0; k < D; k++) a += p[k] * W2[k * D + t];
        q[t] = a;
    }
    __syncthreads();
    float acc = mb1[t];
#pragma unroll
    for (int k = 0; k < D; k++) acc += q[k] * mW1[k * H + t];
    red[t] = fmaxf(acc, 0.f) * mW2[t];
    __syncthreads();
    for (int s = H / 2; s > 0; s >>= 1) {
        if (t < s) red[t] += red[t + s];
        __syncthreads();
    }
    if (t == 0) out[g] = 1.f / (1.f + expf(-(red[0] + mb2[0])));
}

// ---------------------------------------------------------------------------
extern "C" void kernel_launch(void* const* d_in, const int* in_sizes, int n_in,
                              void* d_out, int out_size) {
    const int*   edge_index = (const int*)d_in[0];
    const int*   batch      = (const int*)d_in[1];
    const float* emb        = (const float*)d_in[2];
    const float* W1         = (const float*)d_in[3];
    const float* b1         = (const float*)d_in[4];
    const float* W2         = (const float*)d_in[5];
    const float* b2         = (const float*)d_in[6];
    const float* mW1        = (const float*)d_in[7];
    const float* mb1        = (const float*)d_in[8];
    const float* mW2        = (const float*)d_in[9];
    const float* mb2        = (const float*)d_in[10];
    float* out = (float*)d_out;

    int E = in_sizes[0] / 2;
    const int* src = edge_index;
    const int* dst = edge_index + E;

    void *p_z, *p_x, *p_h;
    cudaGetSymbolAddress(&p_z, g_z);
    cudaGetSymbolAddress(&p_x, g_x);
    cudaGetSymbolAddress(&p_h, g_h);
    float* xbuf = (float*)p_x;
    float* hbuf = (float*)p_h;

    const int TPB = 256;

    // One memset clears cursor + pool + cnt; then CSR fill.
    cudaMemsetAsync(p_z, 0, sizeof(ZeroRegion));
    fill_kernel<<<(E + TPB - 1) / TPB, TPB>>>(src, dst, E);

    // ---- Layer 1: x' = (emb @ W1)*dinv ; y' = relu(Agg(x') + b1)*dinv
    gemm64_kernel<<<N_NODES / 32, 256>>>(emb, W1, xbuf);
    gather_kernel<1><<<N_NODES * 16 / TPB, TPB>>>(
        (const ulonglong2*)xbuf, (float4*)hbuf, (const float4*)b1, batch);

    // ---- Layer 2 aggregation fused with pool: reds into g_z.pool/g_z.cnt
    gather_kernel<0><<<N_NODES * 16 / TPB, TPB>>>(
        (const ulonglong2*)hbuf, (float4*)xbuf, (const float4*)b2, batch);

    // ---- Head (W2/b2 + MLP)
    mlp_kernel<<<N_GRAPHS, H>>>(W2, b2, mW1, mb1, mW2, mb2, out);
}

// round 12
// speedup vs baseline: 1.0342x; 1.0342x over previous
#include <cuda_runtime.h>
#include <math.h>

#define N_NODES 100000
#define N_GRAPHS 1000
#define D 64
#define H 128
#define CAP 64            // max in-degree capacity (actual max ~32 for Poisson(10)+ring)
#define ZROW N_NODES      // zero-row index (stays zero: statics zero-init, never written)

// Scratch (alloc-free rule: __device__ globals). cursor/pool/cnt share one
// struct so a single memset clears all per-run state.
struct ZeroRegion {
    int   cursor[N_NODES];      // becomes in-degree after fill
    float pool[N_GRAPHS * D];
    float cnt[N_GRAPHS];
};
__device__ ZeroRegion g_z;
__device__ int   g_esrc[N_NODES * CAP];        // bucketed edge lists (25.6 MB)
__device__ float g_x[(N_NODES + 1) * D];       // +1 zero row for pad loads
__device__ float g_h[(N_NODES + 1) * D];       // +1 zero row for pad loads

// ---------------------------------------------------------------------------
// Bucketed CSR fill: cursor counts in-degree, esrc[d*CAP + pos] = s.
__global__ void fill_kernel(const int* __restrict__ src,
                            const int* __restrict__ dst, int E) {
    int i = blockIdx.x * blockDim.x + threadIdx.x;
    if (i >= E) return;
    int d = dst[i];
    int pos = atomicAdd(&g_z.cursor[d], 1);
    if (pos < CAP) g_esrc[(size_t)d * CAP + pos] = src[i];
}

// ---------------------------------------------------------------------------
// Y[N,64] = (X[N,64] @ W[64,64]) * rsqrt(deg[row]+1)
__global__ void gemm64_kernel(const float* __restrict__ X,
                              const float* __restrict__ W,
                              float* __restrict__ Y) {
    __shared__ float sW[D * D];
    __shared__ float sx[32 * D];
    int t = threadIdx.x;
    int row0 = blockIdx.x * 32;
    for (int i = t; i < D * D; i += 256) sW[i] = W[i];
    for (int i = t; i < 32 * D; i += 256) sx[i] = X[row0 * D + i];
    __syncthreads();
    int j = t & 63;
    int rg = t >> 6;
    float acc[8];
#pragma unroll
    for (int i = 0; i < 8; i++) acc[i] = 0.f;
#pragma unroll
    for (int k = 0; k < D; k++) {
        float w = sW[k * D + j];
#pragma unroll
        for (int i = 0; i < 8; i++)
            acc[i] += sx[(rg * 8 + i) * D + k] * w;
    }
#pragma unroll
    for (int i = 0; i < 8; i++) {
        int row = row0 + rg * 8 + i;
        float di = rsqrtf((float)(min(g_z.cursor[row], CAP) + 1));
        Y[row * D + j] = acc[i] * di;
    }
}

// ---------------------------------------------------------------------------
// Gather, half-warp (16 lanes x float4) per node. Input pre-scaled by
// dinv[src]. Fixed-trip unrolled loop, zero-row pad for out-of-degree lanes,
// TWO independent float4 accumulators (8 FADD chains) for latency hiding.
//   t[n] = dinv[n] * (sum_{s in N(n)} x'[s] + x'[n])
//   MODE 1 (layer 1): out[n] = relu(t[n] + b) * dinv[n]        -> write g_h
//   MODE 0 (layer 2): red.v4  g_z.pool[batch[n]] += t[n]; cnt  -> no z buffer
template <int MODE>
__global__ void __launch_bounds__(256, 6)
gather_kernel(const float4* __restrict__ X4,
              float4* __restrict__ out,
              const float4* __restrict__ b4,
              const int* __restrict__ batch) {
    int node = (blockIdx.x * blockDim.x + threadIdx.x) >> 4;
    int lane = threadIdx.x & 31;
    int hl = lane & 15;
    int deg = min(g_z.cursor[node], CAP);
    int maxdeg = max(deg, __shfl_xor_sync(0xffffffffu, deg, 16));
    const int* rowp = g_esrc + (size_t)node * CAP;
    float4 acc0 = make_float4(0.f, 0.f, 0.f, 0.f);
    float4 acc1 = make_float4(0.f, 0.f, 0.f, 0.f);
    for (int j = 0; j < maxdeg; j += 16) {
        int s = ((j + hl) < deg) ? rowp[j + hl] : ZROW;
#pragma unroll
        for (int i = 0; i < 16; i += 2) {
            int si0 = __shfl_sync(0xffffffffu, s, (lane & 16) + i);
            int si1 = __shfl_sync(0xffffffffu, s, (lane & 16) + i + 1);
            float4 v0 = X4[(size_t)si0 * 16 + hl];
            float4 v1 = X4[(size_t)si1 * 16 + hl];
            acc0.x += v0.x; acc0.y += v0.y; acc0.z += v0.z; acc0.w += v0.w;
            acc1.x += v1.x; acc1.y += v1.y; acc1.z += v1.z; acc1.w += v1.w;
        }
    }
    // self term + merge accumulators
    float4 xv = X4[(size_t)node * 16 + hl];
    float di = rsqrtf((float)(deg + 1));
    float4 o;
    o.x = (acc0.x + acc1.x + xv.x) * di;
    o.y = (acc0.y + acc1.y + xv.y) * di;
    o.z = (acc0.z + acc1.z + xv.z) * di;
    o.w = (acc0.w + acc1.w + xv.w) * di;
    if (MODE == 1) {
        float4 bb = b4[hl];
        o.x = fmaxf(o.x + bb.x, 0.f) * di;
        o.y = fmaxf(o.y + bb.y, 0.f) * di;
        o.z = fmaxf(o.z + bb.z, 0.f) * di;
        o.w = fmaxf(o.w + bb.w, 0.f) * di;
        out[(size_t)node * 16 + hl] = o;
    } else {
        int g = __ldg(batch + node);
        float* p = g_z.pool + g * D + hl * 4;
        asm volatile("red.global.add.v4.f32 [%0], {%1, %2, %3, %4};"
                     :: "l"(p), "f"(o.x), "f"(o.y), "f"(o.z), "f"(o.w)
                     : "memory");
        if (hl == 0) atomicAdd(&g_z.cnt[g], 1.f);
    }
}

// ---------------------------------------------------------------------------
// Head: q = mean(z) @ W2 + b2 ; out = sigmoid(relu(q @ mW1 + mb1) @ mW2 + mb2)
__global__ void mlp_kernel(const float* __restrict__ W2,
                           const float* __restrict__ b2,
                           const float* __restrict__ mW1,
                           const float* __restrict__ mb1,
                           const float* __restrict__ mW2,
                           const float* __restrict__ mb2,
                           float* __restrict__ out) {
    __shared__ float p[D];
    __shared__ float q[D];
    __shared__ float red[H];
    int g = blockIdx.x, t = threadIdx.x;
    if (t < D) {
        float c = fmaxf(g_z.cnt[g], 1.f);
        p[t] = g_z.pool[g * D + t] / c;
    }
    __syncthreads();
    if (t < D) {
        float a = b2[t];
#pragma unroll
        for (int k = 0; k < D; k++) a += p[k] * W2[k * D + t];
        q[t] = a;
    }
    __syncthreads();
    float acc = mb1[t];
#pragma unroll
    for (int k = 0; k < D; k++) acc += q[k] * mW1[k * H + t];
    red[t] = fmaxf(acc, 0.f) * mW2[t];
    __syncthreads();
    for (int s = H / 2; s > 0; s >>= 1) {
        if (t < s) red[t] += red[t + s];
        __syncthreads();
    }
    if (t == 0) out[g] = 1.f / (1.f + expf(-(red[0] + mb2[0])));
}

// ---------------------------------------------------------------------------
extern "C" void kernel_launch(void* const* d_in, const int* in_sizes, int n_in,
                              void* d_out, int out_size) {
    const int*   edge_index = (const int*)d_in[0];
    const int*   batch      = (const int*)d_in[1];
    const float* emb        = (const float*)d_in[2];
    const float* W1         = (const float*)d_in[3];
    const float* b1         = (const float*)d_in[4];
    const float* W2         = (const float*)d_in[5];
    const float* b2         = (const float*)d_in[6];
    const float* mW1        = (const float*)d_in[7];
    const float* mb1        = (const float*)d_in[8];
    const float* mW2        = (const float*)d_in[9];
    const float* mb2        = (const float*)d_in[10];
    float* out = (float*)d_out;

    int E = in_sizes[0] / 2;
    const int* src = edge_index;
    const int* dst = edge_index + E;

    void *p_z, *p_x, *p_h;
    cudaGetSymbolAddress(&p_z, g_z);
    cudaGetSymbolAddress(&p_x, g_x);
    cudaGetSymbolAddress(&p_h, g_h);
    float* xbuf = (float*)p_x;
    float* hbuf = (float*)p_h;

    const int TPB = 256;

    // One memset clears cursor + pool + cnt; then CSR fill.
    cudaMemsetAsync(p_z, 0, sizeof(ZeroRegion));
    fill_kernel<<<(E + TPB - 1) / TPB, TPB>>>(src, dst, E);

    // ---- Layer 1: x' = (emb @ W1)*dinv ; y' = relu(Agg(x') + b1)*dinv
    gemm64_kernel<<<N_NODES / 32, 256>>>(emb, W1, xbuf);
    gather_kernel<1><<<N_NODES * 16 / TPB, TPB>>>(
        (const float4*)xbuf, (float4*)hbuf, (const float4*)b1, batch);

    // ---- Layer 2 aggregation fused with pool: reds into g_z.pool/g_z.cnt
    gather_kernel<0><<<N_NODES * 16 / TPB, TPB>>>(
        (const float4*)hbuf, (float4*)xbuf, (const float4*)b2, batch);

    // ---- Head (W2/b2 + MLP)
    mlp_kernel<<<N_GRAPHS, H>>>(W2, b2, mW1, mb1, mW2, mb2, out);
}

// round 13
// speedup vs baseline: 1.0658x; 1.0306x over previous
#include <cuda_runtime.h>
#include <math.h>

#define N_NODES 100000
#define N_GRAPHS 1000
#define D 64
#define H 128
#define CAP 64            // max in-degree capacity (actual max ~32 for Poisson(10)+ring)
#define ZROW N_NODES      // zero-row index (stays zero: statics zero-init, never written)

// Scratch (alloc-free rule: __device__ globals). cursor/pool/cnt share one
// struct so a single memset clears all per-run state.
struct ZeroRegion {
    int   cursor[N_NODES];      // becomes in-degree after fill
    float pool[N_GRAPHS * D];
    float cnt[N_GRAPHS];
};
__device__ ZeroRegion g_z;
__device__ int   g_esrc[N_NODES * CAP];        // bucketed edge lists (25.6 MB)
__device__ float g_x[(N_NODES + 1) * D];       // +1 zero row for pad loads
__device__ float g_h[(N_NODES + 1) * D];       // +1 zero row for pad loads

// ---------------------------------------------------------------------------
// Bucketed CSR fill: cursor counts in-degree, esrc[d*CAP + pos] = s.
__global__ void fill_kernel(const int* __restrict__ src,
                            const int* __restrict__ dst, int E) {
    int i = blockIdx.x * blockDim.x + threadIdx.x;
    if (i >= E) return;
    int d = dst[i];
    int pos = atomicAdd(&g_z.cursor[d], 1);
    if (pos < CAP) g_esrc[(size_t)d * CAP + pos] = src[i];
}

// ---------------------------------------------------------------------------
// Y[N,64] = (X[N,64] @ W[64,64]) * rsqrt(deg[row]+1)
__global__ void gemm64_kernel(const float* __restrict__ X,
                              const float* __restrict__ W,
                              float* __restrict__ Y) {
    __shared__ float sW[D * D];
    __shared__ float sx[32 * D];
    int t = threadIdx.x;
    int row0 = blockIdx.x * 32;
    for (int i = t; i < D * D; i += 256) sW[i] = W[i];
    for (int i = t; i < 32 * D; i += 256) sx[i] = X[row0 * D + i];
    __syncthreads();
    int j = t & 63;
    int rg = t >> 6;
    float acc[8];
#pragma unroll
    for (int i = 0; i < 8; i++) acc[i] = 0.f;
#pragma unroll
    for (int k = 0; k < D; k++) {
        float w = sW[k * D + j];
#pragma unroll
        for (int i = 0; i < 8; i++)
            acc[i] += sx[(rg * 8 + i) * D + k] * w;
    }
#pragma unroll
    for (int i = 0; i < 8; i++) {
        int row = row0 + rg * 8 + i;
        float di = rsqrtf((float)(min(g_z.cursor[row], CAP) + 1));
        Y[row * D + j] = acc[i] * di;
    }
}

// ---------------------------------------------------------------------------
// Gather, half-warp (16 lanes x float4) per node. Input pre-scaled by
// dinv[src]. Fixed-trip unrolled loop, zero-row pad, dual accumulators.
//   t[n] = dinv[n] * (sum_{s in N(n)} x'[s] + x'[n])
//   MODE 1 (layer 1): out[n] = relu(t[n] + b) * dinv[n]  -> write g_h
//   MODE 0 (layer 2): block-level segmented pool flush: stage z rows in smem,
//                     fold the block's 16 consecutive nodes along sorted-batch
//                     segments, ~2 red.v4 per column per block (8x fewer reds).
template <int MODE>
__global__ void __launch_bounds__(256, 6)
gather_kernel(const float4* __restrict__ X4,
              float4* __restrict__ out,
              const float4* __restrict__ b4,
              const int* __restrict__ batch) {
    int tid = threadIdx.x;
    int node = (blockIdx.x * blockDim.x + tid) >> 4;
    int lane = tid & 31;
    int hl = lane & 15;
    int deg = min(g_z.cursor[node], CAP);
    int maxdeg = max(deg, __shfl_xor_sync(0xffffffffu, deg, 16));
    const int* rowp = g_esrc + (size_t)node * CAP;
    float4 acc0 = make_float4(0.f, 0.f, 0.f, 0.f);
    float4 acc1 = make_float4(0.f, 0.f, 0.f, 0.f);
    for (int j = 0; j < maxdeg; j += 16) {
        int s = ((j + hl) < deg) ? rowp[j + hl] : ZROW;
#pragma unroll
        for (int i = 0; i < 16; i += 2) {
            int si0 = __shfl_sync(0xffffffffu, s, (lane & 16) + i);
            int si1 = __shfl_sync(0xffffffffu, s, (lane & 16) + i + 1);
            float4 v0 = X4[(size_t)si0 * 16 + hl];
            float4 v1 = X4[(size_t)si1 * 16 + hl];
            acc0.x += v0.x; acc0.y += v0.y; acc0.z += v0.z; acc0.w += v0.w;
            acc1.x += v1.x; acc1.y += v1.y; acc1.z += v1.z; acc1.w += v1.w;
        }
    }
    // self term + merge accumulators
    float4 xv = X4[(size_t)node * 16 + hl];
    float di = rsqrtf((float)(deg + 1));
    float4 o;
    o.x = (acc0.x + acc1.x + xv.x) * di;
    o.y = (acc0.y + acc1.y + xv.y) * di;
    o.z = (acc0.z + acc1.z + xv.z) * di;
    o.w = (acc0.w + acc1.w + xv.w) * di;
    if (MODE == 1) {
        float4 bb = b4[hl];
        o.x = fmaxf(o.x + bb.x, 0.f) * di;
        o.y = fmaxf(o.y + bb.y, 0.f) * di;
        o.z = fmaxf(o.z + bb.z, 0.f) * di;
        o.w = fmaxf(o.w + bb.w, 0.f) * di;
        out[(size_t)node * 16 + hl] = o;
    } else {
        // Stage z rows + graph ids in smem; fold segments; sparse flush.
        __shared__ float4 sZ[16][16];   // [node-in-block][column chunk]
        __shared__ int    sB[16];
        int nib = tid >> 4;             // node-in-block 0..15
        sZ[nib][hl] = o;
        if (hl == 0) sB[nib] = __ldg(batch + node);
        __syncthreads();
        if (tid < 16) {
            int c = tid;                // column chunk this thread folds
            float4 z = sZ[0][c];
            int curg = sB[0];
            int run = 1;
            for (int k = 1; k < 16; k++) {
                int bk = sB[k];
                float4 v = sZ[k][c];
                if (bk != curg) {
                    float* p = g_z.pool + curg * D + c * 4;
                    asm volatile("red.global.add.v4.f32 [%0], {%1, %2, %3, %4};"
                                 :: "l"(p), "f"(z.x), "f"(z.y), "f"(z.z), "f"(z.w)
                                 : "memory");
                    if (c == 0) atomicAdd(&g_z.cnt[curg], (float)run);
                    z = v; curg = bk; run = 1;
                } else {
                    z.x += v.x; z.y += v.y; z.z += v.z; z.w += v.w;
                    run++;
                }
            }
            float* p = g_z.pool + curg * D + c * 4;
            asm volatile("red.global.add.v4.f32 [%0], {%1, %2, %3, %4};"
                         :: "l"(p), "f"(z.x), "f"(z.y), "f"(z.z), "f"(z.w)
                         : "memory");
            if (c == 0) atomicAdd(&g_z.cnt[curg], (float)run);
        }
    }
}

// ---------------------------------------------------------------------------
// Head: q = mean(z) @ W2 + b2 ; out = sigmoid(relu(q @ mW1 + mb1) @ mW2 + mb2)
__global__ void mlp_kernel(const float* __restrict__ W2,
                           const float* __restrict__ b2,
                           const float* __restrict__ mW1,
                           const float* __restrict__ mb1,
                           const float* __restrict__ mW2,
                           const float* __restrict__ mb2,
                           float* __restrict__ out) {
    __shared__ float p[D];
    __shared__ float q[D];
    __shared__ float red[H];
    int g = blockIdx.x, t = threadIdx.x;
    if (t < D) {
        float c = fmaxf(g_z.cnt[g], 1.f);
        p[t] = g_z.pool[g * D + t] / c;
    }
    __syncthreads();
    if (t < D) {
        float a = b2[t];
#pragma unroll
        for (int k = 0; k < D; k++) a += p[k] * W2[k * D + t];
        q[t] = a;
    }
    __syncthreads();
    float acc = mb1[t];
#pragma unroll
    for (int k = 0; k < D; k++) acc += q[k] * mW1[k * H + t];
    red[t] = fmaxf(acc, 0.f) * mW2[t];
    __syncthreads();
    for (int s = H / 2; s > 0; s >>= 1) {
        if (t < s) red[t] += red[t + s];
        __syncthreads();
    }
    if (t == 0) out[g] = 1.f / (1.f + expf(-(red[0] + mb2[0])));
}

// ---------------------------------------------------------------------------
extern "C" void kernel_launch(void* const* d_in, const int* in_sizes, int n_in,
                              void* d_out, int out_size) {
    const int*   edge_index = (const int*)d_in[0];
    const int*   batch      = (const int*)d_in[1];
    const float* emb        = (const float*)d_in[2];
    const float* W1         = (const float*)d_in[3];
    const float* b1         = (const float*)d_in[4];
    const float* W2         = (const float*)d_in[5];
    const float* b2         = (const float*)d_in[6];
    const float* mW1        = (const float*)d_in[7];
    const float* mb1        = (const float*)d_in[8];
    const float* mW2        = (const float*)d_in[9];
    const float* mb2        = (const float*)d_in[10];
    float* out = (float*)d_out;

    int E = in_sizes[0] / 2;
    const int* src = edge_index;
    const int* dst = edge_index + E;

    void *p_z, *p_x, *p_h;
    cudaGetSymbolAddress(&p_z, g_z);
    cudaGetSymbolAddress(&p_x, g_x);
    cudaGetSymbolAddress(&p_h, g_h);
    float* xbuf = (float*)p_x;
    float* hbuf = (float*)p_h;

    const int TPB = 256;

    // One memset clears cursor + pool + cnt; then CSR fill.
    cudaMemsetAsync(p_z, 0, sizeof(ZeroRegion));
    fill_kernel<<<(E + TPB - 1) / TPB, TPB>>>(src, dst, E);

    // ---- Layer 1: x' = (emb @ W1)*dinv ; y' = relu(Agg(x') + b1)*dinv
    gemm64_kernel<<<N_NODES / 32, 256>>>(emb, W1, xbuf);
    gather_kernel<1><<<N_NODES * 16 / TPB, TPB>>>(
        (const float4*)xbuf, (float4*)hbuf, (const float4*)b1, batch);

    // ---- Layer 2 aggregation + segmented pool flush
    gather_kernel<0><<<N_NODES * 16 / TPB, TPB>>>(
        (const float4*)hbuf, (float4*)xbuf, (const float4*)b2, batch);

    // ---- Head (W2/b2 + MLP)
    mlp_kernel<<<N_GRAPHS, H>>>(W2, b2, mW1, mb1, mW2, mb2, out);
}